// round 2
// baseline (speedup 1.0000x reference)
#include <cuda_runtime.h>
#include <math.h>

#define NB 4096
#define NM 4
#define NL 4
#define ND 8
#define NSTATE 4096

// ---------------- device-global gate storage ----------------
// BS gates: [L][2][6] of 64x64 complex, stored TRANSPOSED: G[jp*64+ip] = U[ip][jp]
__device__ float2 g_bs[48 * 4096];
__device__ float2 g_rotpre[32 * 8];    // [L][2][4] diag vectors
__device__ float2 g_rotpost[48 * 8];   // [L][2][6] diag vectors
__device__ float2 g_sq[16 * 64];       // [L][4] 8x8 transposed
__device__ float2 g_dp[16 * 64];       // [L][4] 8x8 transposed
__device__ float2 g_kerr[16 * 8];      // [L][4] diag vectors
__device__ float  g_dx[NB * NM * 64];  // per-sample real encoding gates, transposed

__constant__ int c_pi[6] = {0,0,0,1,1,2};
__constant__ int c_pj[6] = {1,2,3,2,3,3};
__constant__ int c_oa[6] = {2,1,1,0,0,0};
__constant__ int c_ob[6] = {3,3,2,3,2,1};

// ---------------- small expm (scaling-and-squaring Taylor) ----------------
__device__ void matmul_c(const float2* X, const float2* Y, float2* Z, int n, float scale) {
    for (int i = 0; i < n; i++)
        for (int j = 0; j < n; j++) {
            float ar = 0.f, ai = 0.f;
            for (int m = 0; m < n; m++) {
                float2 a = X[i*8+m], b = Y[m*8+j];
                ar += a.x*b.x - a.y*b.y;
                ai += a.x*b.y + a.y*b.x;
            }
            Z[i*8+j] = make_float2(ar*scale, ai*scale);
        }
}

__device__ void expm_c8(const float2* H, float2* E, int n) {
    float norm = 0.f;
    for (int i = 0; i < n; i++) {
        float r = 0.f;
        for (int j = 0; j < n; j++) r += fabsf(H[i*8+j].x) + fabsf(H[i*8+j].y);
        norm = fmaxf(norm, r);
    }
    int s = 0;
    while (norm > 0.5f && s < 30) { norm *= 0.5f; s++; }
    float sc = ldexpf(1.f, -s);
    float2 T[64], P[64], Q[64];
    for (int i = 0; i < n; i++)
        for (int j = 0; j < n; j++) {
            float2 h = H[i*8+j];
            float2 tv = make_float2(h.x*sc, h.y*sc);
            T[i*8+j] = tv; P[i*8+j] = tv; E[i*8+j] = tv;
        }
    for (int i = 0; i < n; i++) E[i*8+i].x += 1.f;
    for (int k = 2; k <= 16; k++) {
        matmul_c(P, T, Q, n, 1.f/(float)k);
        for (int i = 0; i < n; i++)
            for (int j = 0; j < n; j++) {
                P[i*8+j] = Q[i*8+j];
                E[i*8+j].x += Q[i*8+j].x;
                E[i*8+j].y += Q[i*8+j].y;
            }
    }
    for (int it = 0; it < s; it++) {
        matmul_c(E, E, Q, n, 1.f);
        for (int i = 0; i < n; i++)
            for (int j = 0; j < n; j++) E[i*8+j] = Q[i*8+j];
    }
}

__device__ void matmul_r(const float* X, const float* Y, float* Z, int n, float scale) {
    for (int i = 0; i < n; i++)
        for (int j = 0; j < n; j++) {
            float a = 0.f;
            for (int m = 0; m < n; m++) a += X[i*8+m] * Y[m*8+j];
            Z[i*8+j] = a * scale;
        }
}

__device__ void expm_r8(const float* H, float* E, int n) {
    float norm = 0.f;
    for (int i = 0; i < n; i++) {
        float r = 0.f;
        for (int j = 0; j < n; j++) r += fabsf(H[i*8+j]);
        norm = fmaxf(norm, r);
    }
    int s = 0;
    while (norm > 0.5f && s < 30) { norm *= 0.5f; s++; }
    float sc = ldexpf(1.f, -s);
    float T[64], P[64], Q[64];
    for (int i = 0; i < n; i++)
        for (int j = 0; j < n; j++) {
            float tv = H[i*8+j] * sc;
            T[i*8+j] = tv; P[i*8+j] = tv; E[i*8+j] = tv;
        }
    for (int i = 0; i < n; i++) E[i*8+i] += 1.f;
    for (int k = 2; k <= 16; k++) {
        matmul_r(P, T, Q, n, 1.f/(float)k);
        for (int i = 0; i < n; i++)
            for (int j = 0; j < n; j++) { P[i*8+j] = Q[i*8+j]; E[i*8+j] += Q[i*8+j]; }
    }
    for (int it = 0; it < s; it++) {
        matmul_r(E, E, Q, n, 1.f);
        for (int i = 0; i < n; i++)
            for (int j = 0; j < n; j++) E[i*8+j] = Q[i*8+j];
    }
}

// ---------------- precompute shared gates ----------------
__global__ void precompute_kernel(
    const float* th1, const float* ph1, const float* th2, const float* ph2,
    const float* dr, const float* dph, const float* sr, const float* sph,
    const float* kerr)
{
    int tid = blockIdx.x * blockDim.x + threadIdx.x;
    if (tid < 720) {
        // beamsplitter: one photon-number block per thread (48 gates x 15 totals)
        int g  = tid / 15, tt = tid % 15;
        int l  = g / 12, k = (g / 6) % 2, p = g % 6;
        const float* TH = k ? th2 : th1;
        const float* PH = k ? ph2 : ph1;
        int mi = c_pi[p], mj = c_pj[p];
        float theta = TH[(l*4+mi)*4 + mj];
        float phi   = PH[(l*4+mi)*4 + mj];
        int lo = tt > 7 ? tt - 7 : 0;
        int hi = tt < 7 ? tt : 7;
        int n  = hi - lo + 1;
        float2 H[64];
        for (int q = 0; q < 64; q++) H[q] = make_float2(0.f, 0.f);
        float cp = cosf(phi), sp = sinf(phi);
        for (int r = 0; r < n; r++) {
            int j1 = lo + r, j2 = tt - j1;
            if (r >= 1) {   // theta e^{i phi} sqrt(j1) sqrt(j2+1): (j1,j2)->(j1-1,j2+1)
                float mag = theta * sqrtf((float)(j1 * (j2 + 1)));
                H[(r-1)*8 + r] = make_float2(mag*cp, mag*sp);
            }
            if (r <= n - 2) {  // -theta e^{-i phi} sqrt(j1+1) sqrt(j2): (j1,j2)->(j1+1,j2-1)
                float mag = theta * sqrtf((float)((j1 + 1) * j2));
                H[(r+1)*8 + r] = make_float2(-mag*cp, mag*sp);
            }
        }
        float2 E[64];
        expm_c8(H, E, n);
        float2* dst = g_bs + g * 4096;
        for (int ir = 0; ir < n; ir++) {
            int ipp = (lo + ir) * 8 + (tt - lo - ir);
            for (int jr = 0; jr < n; jr++) {
                int jpp = (lo + jr) * 8 + (tt - lo - jr);
                dst[jpp*64 + ipp] = E[ir*8 + jr];   // transposed
            }
        }
    } else if (tid < 736) {
        // squeeze: S(z)=exp(0.5(conj z A^2 - z AD^2)), z = r e^{i p}
        int idx = tid - 720;
        float r = sr[idx], p = sph[idx];
        float2 H[64];
        for (int q = 0; q < 64; q++) H[q] = make_float2(0.f, 0.f);
        float cp = cosf(p), sp = sinf(p);
        for (int jj = 2; jj < 8; jj++) {
            float m = 0.5f * r * sqrtf((float)(jj * (jj - 1)));
            H[(jj-2)*8 + jj] = make_float2(m*cp, -m*sp);
            H[jj*8 + jj-2]   = make_float2(-m*cp, -m*sp);
        }
        float2 E[64];
        expm_c8(H, E, 8);
        float2* dst = g_sq + idx * 64;
        for (int i = 0; i < 8; i++)
            for (int j = 0; j < 8; j++) dst[j*8+i] = E[i*8+j];
    } else if (tid < 752) {
        // layer displacement: alpha = (r cos p) e^{i r sin p}
        int idx = tid - 736;
        float r = dr[idx], p = dph[idx];
        float amag = r * cosf(p);
        float aph  = r * sinf(p);
        float2 al = make_float2(amag * cosf(aph), amag * sinf(aph));
        float2 H[64];
        for (int q = 0; q < 64; q++) H[q] = make_float2(0.f, 0.f);
        for (int ii = 1; ii < 8; ii++) {
            float rt = sqrtf((float)ii);
            H[ii*8 + ii-1] = make_float2(al.x*rt, al.y*rt);      //  alpha * AD
            H[(ii-1)*8 + ii] = make_float2(-al.x*rt, al.y*rt);   // -conj(alpha) * A
        }
        float2 E[64];
        expm_c8(H, E, 8);
        float2* dst = g_dp + idx * 64;
        for (int i = 0; i < 8; i++)
            for (int j = 0; j < 8; j++) dst[j*8+i] = E[i*8+j];
    } else if (tid < 784) {
        int idx = tid - 752;       // l*8 + k*4 + i
        int l = idx >> 3, k = (idx >> 2) & 1, i = idx & 3;
        const float* PH = k ? ph2 : ph1;
        float phi = PH[(l*4+i)*4 + i];
        float2* dst = g_rotpre + idx * 8;
        for (int nn = 0; nn < 8; nn++) dst[nn] = make_float2(cosf(phi*nn), sinf(phi*nn));
    } else if (tid < 832) {
        int idx = tid - 784;       // l*12 + k*6 + p
        int l = idx / 12, k = (idx / 6) % 2, p = idx % 6;
        const float* PH = k ? ph2 : ph1;
        float phi = PH[(l*4 + c_pj[p])*4 + c_pi[p]];
        float2* dst = g_rotpost + idx * 8;
        for (int nn = 0; nn < 8; nn++) dst[nn] = make_float2(cosf(phi*nn), sinf(phi*nn));
    } else if (tid < 848) {
        int idx = tid - 832;
        float kp = kerr[idx];
        float2* dst = g_kerr + idx * 8;
        for (int nn = 0; nn < 8; nn++) {
            float a = kp * (float)(nn * nn);
            dst[nn] = make_float2(cosf(a), sinf(a));
        }
    }
}

// ---------------- per-sample encoding displacement (real expm) ----------------
__global__ void encode_kernel(const float* x) {
    int tid = blockIdx.x * blockDim.x + threadIdx.x;
    if (tid >= NB * NM) return;
    float xv = x[tid];
    float H[64];
    for (int q = 0; q < 64; q++) H[q] = 0.f;
    for (int ii = 1; ii < 8; ii++) {
        float r = xv * sqrtf((float)ii);
        H[ii*8 + ii-1] = r;       // x * AD
        H[(ii-1)*8 + ii] = -r;    // -x * A
    }
    float E[64];
    expm_r8(H, E, 8);
    float* dst = g_dx + tid * 64;
    for (int i = 0; i < 8; i++)
        for (int j = 0; j < 8; j++) dst[j*8+i] = E[i*8+j];   // transposed
}

// ---------------- main simulation ----------------
__device__ __forceinline__ void apply1c(float2* st, const float2* G, int m, int t) {
    int sh = 3 * (3 - m);
    int s  = 1 << sh;
    int i  = t & 7;
    float2 g[8];
    #pragma unroll
    for (int j = 0; j < 8; j++) g[j] = G[j*8 + i];
    int sb = t >> 3;
    float2 acc[16];
    #pragma unroll
    for (int k = 0; k < 16; k++) {
        int sl = sb + k * 32;
        int base = ((sl >> sh) << (sh + 3)) | (sl & (s - 1));
        float ar = 0.f, ai = 0.f;
        #pragma unroll
        for (int j = 0; j < 8; j++) {
            float2 v = st[base + (j << sh)];
            ar += g[j].x*v.x - g[j].y*v.y;
            ai += g[j].x*v.y + g[j].y*v.x;
        }
        acc[k] = make_float2(ar, ai);
    }
    __syncthreads();
    #pragma unroll
    for (int k = 0; k < 16; k++) {
        int sl = sb + k * 32;
        int base = ((sl >> sh) << (sh + 3)) | (sl & (s - 1));
        st[base + (i << sh)] = acc[k];
    }
    __syncthreads();
}

__device__ __forceinline__ void apply1r(float2* st, const float* G, int m, int t) {
    int sh = 3 * (3 - m);
    int s  = 1 << sh;
    int i  = t & 7;
    float g[8];
    #pragma unroll
    for (int j = 0; j < 8; j++) g[j] = G[j*8 + i];
    int sb = t >> 3;
    float2 acc[16];
    #pragma unroll
    for (int k = 0; k < 16; k++) {
        int sl = sb + k * 32;
        int base = ((sl >> sh) << (sh + 3)) | (sl & (s - 1));
        float ar = 0.f, ai = 0.f;
        #pragma unroll
        for (int j = 0; j < 8; j++) {
            float2 v = st[base + (j << sh)];
            ar += g[j] * v.x;
            ai += g[j] * v.y;
        }
        acc[k] = make_float2(ar, ai);
    }
    __syncthreads();
    #pragma unroll
    for (int k = 0; k < 16; k++) {
        int sl = sb + k * 32;
        int base = ((sl >> sh) << (sh + 3)) | (sl & (s - 1));
        st[base + (i << sh)] = acc[k];
    }
    __syncthreads();
}

__device__ __forceinline__ void apply2c(float2* st, const float2* G, int p, int t) {
    int m1 = c_pi[p], m2 = c_pj[p], oa = c_oa[p], obm = c_ob[p];
    int s1 = 1 << (3 * (3 - m1)), s2 = 1 << (3 * (3 - m2));
    int sa = 1 << (3 * (3 - oa)), sb = 1 << (3 * (3 - obm));
    int ip = t & 63;
    int i1 = ip >> 3, i2 = ip & 7;
    int tt = i1 + i2;
    int lo = tt > 7 ? tt - 7 : 0;
    int hi = tt < 7 ? tt : 7;
    int cnt = hi - lo + 1;
    // photon-number-conserving: only <=8 nonzero inputs per output
    float2 g[8];
    #pragma unroll
    for (int r = 0; r < 8; r++) {
        if (r < cnt) {
            int j1 = lo + r, j2 = tt - j1;
            g[r] = G[(j1*8 + j2) * 64 + ip];
        }
    }
    int ob0 = t >> 6;      // 0..3
    float2 acc[16];
    #pragma unroll
    for (int k = 0; k < 16; k++) {
        int outer = ob0 + (k << 2);
        int base  = (outer >> 3) * sa + (outer & 7) * sb;
        float ar = 0.f, ai = 0.f;
        int addr = base + lo * s1 + (tt - lo) * s2;
        #pragma unroll
        for (int r = 0; r < 8; r++) {
            if (r < cnt) {
                float2 v = st[addr];
                ar += g[r].x*v.x - g[r].y*v.y;
                ai += g[r].x*v.y + g[r].y*v.x;
            }
            addr += s1 - s2;
        }
        acc[k] = make_float2(ar, ai);
    }
    __syncthreads();
    #pragma unroll
    for (int k = 0; k < 16; k++) {
        int outer = ob0 + (k << 2);
        int base  = (outer >> 3) * sa + (outer & 7) * sb;
        st[base + i1 * s1 + i2 * s2] = acc[k];
    }
    __syncthreads();
}

__device__ __forceinline__ void applyDiag(float2* st, const float2* dv, int m, int t) {
    int sh = 3 * (3 - m);
    #pragma unroll
    for (int k = 0; k < 16; k++) {
        int n = t + (k << 8);
        float2 d = dv[(n >> sh) & 7];
        float2 v = st[n];
        st[n] = make_float2(v.x*d.x - v.y*d.y, v.x*d.y + v.y*d.x);
    }
    __syncthreads();
}

__device__ __forceinline__ void interferometer(float2* st, int l, int kk, int t) {
    for (int i = 0; i < 4; i++)
        applyDiag(st, g_rotpre + ((l*2 + kk)*4 + i) * 8, i, t);
    for (int p = 0; p < 6; p++) {
        apply2c(st, g_bs + ((l*2 + kk)*6 + p) * 4096, p, t);
        applyDiag(st, g_rotpost + ((l*2 + kk)*6 + p) * 8, c_pj[p], t);
    }
}

__global__ void __launch_bounds__(256) sim_kernel(float* out) {
    __shared__ float2 st[NSTATE];
    __shared__ float red[8][4];
    int t = threadIdx.x;
    int b = blockIdx.x;

    #pragma unroll
    for (int k = 0; k < 16; k++) {
        int n = t + (k << 8);
        st[n] = make_float2(n == 0 ? 1.f : 0.f, 0.f);
    }
    __syncthreads();

    // encoding
    for (int m = 0; m < 4; m++)
        apply1r(st, g_dx + (b*4 + m) * 64, m, t);

    for (int l = 0; l < 4; l++) {
        interferometer(st, l, 0, t);
        for (int w = 0; w < 4; w++) apply1c(st, g_sq + (l*4 + w) * 64, w, t);
        interferometer(st, l, 1, t);
        for (int w = 0; w < 4; w++) apply1c(st, g_dp + (l*4 + w) * 64, w, t);
        for (int w = 0; w < 4; w++) applyDiag(st, g_kerr + (l*4 + w) * 8, w, t);
    }

    // expectation values <n_w>
    float ev0 = 0.f, ev1 = 0.f, ev2 = 0.f, ev3 = 0.f;
    #pragma unroll
    for (int k = 0; k < 16; k++) {
        int n = t + (k << 8);
        float2 v = st[n];
        float pr = v.x*v.x + v.y*v.y;
        ev0 += pr * (float)((n >> 9) & 7);
        ev1 += pr * (float)((n >> 6) & 7);
        ev2 += pr * (float)((n >> 3) & 7);
        ev3 += pr * (float)(n & 7);
    }
    #pragma unroll
    for (int off = 16; off; off >>= 1) {
        ev0 += __shfl_xor_sync(0xffffffffu, ev0, off);
        ev1 += __shfl_xor_sync(0xffffffffu, ev1, off);
        ev2 += __shfl_xor_sync(0xffffffffu, ev2, off);
        ev3 += __shfl_xor_sync(0xffffffffu, ev3, off);
    }
    __syncthreads();
    int warp = t >> 5, lane = t & 31;
    if (lane == 0) {
        red[warp][0] = ev0; red[warp][1] = ev1;
        red[warp][2] = ev2; red[warp][3] = ev3;
    }
    __syncthreads();
    if (t < 4) {
        float s = 0.f;
        for (int w = 0; w < 8; w++) s += red[w][t];
        out[b*4 + t] = s;
    }
}

// ---------------- launch ----------------
extern "C" void kernel_launch(void* const* d_in, const int* in_sizes, int n_in,
                              void* d_out, int out_size) {
    const float* x   = (const float*)d_in[0];
    const float* th1 = (const float*)d_in[1];
    const float* ph1 = (const float*)d_in[2];
    const float* th2 = (const float*)d_in[3];
    const float* ph2 = (const float*)d_in[4];
    const float* dr  = (const float*)d_in[5];
    const float* dph = (const float*)d_in[6];
    const float* sr  = (const float*)d_in[7];
    const float* sph = (const float*)d_in[8];
    const float* kr  = (const float*)d_in[9];

    precompute_kernel<<<4, 256>>>(th1, ph1, th2, ph2, dr, dph, sr, sph, kr);
    encode_kernel<<<64, 256>>>(x);
    sim_kernel<<<NB, 256>>>((float*)d_out);
}